// round 14
// baseline (speedup 1.0000x reference)
#include <cuda_runtime.h>
#include <cstdint>

#define NUSERS 50000
#define NITEMS 50000
#define NNODES 100000
#define DFEAT  256
#define HID    128
#define NEDGES 1600000
#define KLAYERS 3

#define SCAN_BS   1024
#define SCAN_NB   ((NNODES + SCAN_BS - 1) / SCAN_BS)   // 98

// Scratch (static device globals; allocation is forbidden)
__device__ float g_x  [(size_t)NNODES * HID];
__device__ float g_agg[(size_t)NNODES * HID];
__device__ int   g_cnt[NNODES];            // zero-init at load; self-zeroed each call
__device__ int   g_rowptr[NNODES + 1];
__device__ int   g_cur[NNODES];
__device__ int   g_csr[NEDGES];
__device__ int   g_part[SCAN_NB];

__device__ __forceinline__ uint32_t f2tf32(float f) {
    uint32_t u;
    asm("cvt.rna.tf32.f32 %0, %1;" : "=r"(u) : "f"(f));
    return u;
}
__device__ __forceinline__ float lrelu(float v) { return (v > 0.f) ? v : 0.01f * v; }

// ---------------- CSR construction ----------------
__global__ void hist_kernel(const int* __restrict__ dst)
{
    int e = blockIdx.x * blockDim.x + threadIdx.x;
    if (e < NEDGES) atomicAdd(&g_cnt[__ldg(dst + e)], 1);
}

__global__ void scan_blocks_kernel()
{
    __shared__ int sh[SCAN_BS];
    int t = threadIdx.x, b = blockIdx.x;
    int i = b * SCAN_BS + t;
    sh[t] = (i < NNODES) ? g_cnt[i] : 0;
    if (i < NNODES) g_cnt[i] = 0;          // self-zero for the next call
    __syncthreads();
    #pragma unroll
    for (int off = 1; off < SCAN_BS; off <<= 1) {
        int u = (t >= off) ? sh[t - off] : 0;
        __syncthreads();
        sh[t] += u;
        __syncthreads();
    }
    if (i < NNODES) g_rowptr[i + 1] = sh[t];
    if (t == SCAN_BS - 1) g_part[b] = sh[t];
}

__global__ void scan_fin_kernel()
{
    __shared__ int wsum[32];
    int t = threadIdx.x, b = blockIdx.x;
    int v = (t < b) ? g_part[t] : 0;   // b <= 97 < 1024
    #pragma unroll
    for (int o = 16; o > 0; o >>= 1) v += __shfl_down_sync(0xffffffffu, v, o);
    if ((t & 31) == 0) wsum[t >> 5] = v;
    __syncthreads();
    if (t == 0) {
        int s = 0;
        #pragma unroll
        for (int w = 0; w < 32; w++) s += wsum[w];
        wsum[0] = s;
    }
    __syncthreads();
    int off = wsum[0];
    int i = b * SCAN_BS + t;
    int p = 0;
    if (i < NNODES && t > 0) p = g_rowptr[i];
    __syncthreads();
    if (i < NNODES) {
        g_rowptr[i + 1] += off;
        g_cur[i] = off + p;
        if (i == 0) g_rowptr[0] = 0;
    }
}

__global__ void fill_kernel(const int* __restrict__ src, const int* __restrict__ dst)
{
    int e = blockIdx.x * blockDim.x + threadIdx.x;
    if (e >= NEDGES) return;
    int d = __ldg(dst + e);
    int pos = atomicAdd(&g_cur[d], 1);
    g_csr[pos] = __ldg(src + e);
}

// ---------------- CSR aggregation: agg[n] = sum_{e: dst=n} x[src[e]] ----------------
__global__ void __launch_bounds__(256)
agg_csr_kernel(const float* __restrict__ x, float* __restrict__ agg)
{
    int n = blockIdx.x * 8 + (threadIdx.x >> 5);
    if (n >= NNODES) return;
    const int lane = threadIdx.x & 31;
    const int beg = __ldg(&g_rowptr[n]);
    const int end = __ldg(&g_rowptr[n + 1]);

    float4 acc = make_float4(0.f, 0.f, 0.f, 0.f);
    for (int base = beg; base < end; base += 32) {
        int j = base + lane;
        int my = (j < end) ? __ldg(&g_csr[j]) : 0;
        int cnt = min(32, end - base);
        int t = 0;
        for (; t + 4 <= cnt; t += 4) {
            int s0 = __shfl_sync(0xffffffffu, my, t);
            int s1 = __shfl_sync(0xffffffffu, my, t + 1);
            int s2 = __shfl_sync(0xffffffffu, my, t + 2);
            int s3 = __shfl_sync(0xffffffffu, my, t + 3);
            float4 v0 = __ldg(reinterpret_cast<const float4*>(x + (size_t)s0 * HID) + lane);
            float4 v1 = __ldg(reinterpret_cast<const float4*>(x + (size_t)s1 * HID) + lane);
            float4 v2 = __ldg(reinterpret_cast<const float4*>(x + (size_t)s2 * HID) + lane);
            float4 v3 = __ldg(reinterpret_cast<const float4*>(x + (size_t)s3 * HID) + lane);
            acc.x += v0.x; acc.y += v0.y; acc.z += v0.z; acc.w += v0.w;
            acc.x += v1.x; acc.y += v1.y; acc.z += v1.z; acc.w += v1.w;
            acc.x += v2.x; acc.y += v2.y; acc.z += v2.z; acc.w += v2.w;
            acc.x += v3.x; acc.y += v3.y; acc.z += v3.z; acc.w += v3.w;
        }
        for (; t < cnt; t++) {
            int s = __shfl_sync(0xffffffffu, my, t);
            float4 v = __ldg(reinterpret_cast<const float4*>(x + (size_t)s * HID) + lane);
            acc.x += v.x; acc.y += v.y; acc.z += v.z; acc.w += v.w;
        }
    }
    reinterpret_cast<float4*>(agg + (size_t)n * HID)[lane] = acc;
}

// ---------------- users: copy + row L2-normalize + raw fp32 passthrough ----------------
__global__ void user_copy_norm_kernel(const float* __restrict__ ufe, float* __restrict__ x,
                                      float* __restrict__ pass)
{
    int row = blockIdx.x * 8 + (threadIdx.x >> 5);
    if (row >= NUSERS) return;
    int lane = threadIdx.x & 31;
    float4 v = __ldg(reinterpret_cast<const float4*>(ufe + (size_t)row * HID) + lane);
    reinterpret_cast<float4*>(pass + (size_t)row * HID)[lane] = v;
    float ss = v.x * v.x + v.y * v.y + v.z * v.z + v.w * v.w;
    #pragma unroll
    for (int o = 16; o > 0; o >>= 1) ss += __shfl_xor_sync(0xffffffffu, ss, o);
    float s = 1.0f / fmaxf(sqrtf(ss), 1e-12f);
    v.x *= s; v.y *= s; v.z *= s; v.w *= s;
    reinterpret_cast<float4*>(x + (size_t)row * HID)[lane] = v;
}

// ---------------- 256-thread GEMM building blocks (gemm_trans only) ----------------
__device__ __forceinline__ void load_a_chunk(float4 (&v)[4], const float* __restrict__ A,
                                             int row0, int lda, int kb, int M, int tid)
{
    #pragma unroll
    for (int i = 0; i < 4; i++) {
        int q  = tid + i * 256;
        int m  = q >> 3;
        int k4 = q & 7;
        v[i] = make_float4(0.f, 0.f, 0.f, 0.f);
        if (row0 + m < M)
            v[i] = __ldg(reinterpret_cast<const float4*>(A + (size_t)(row0 + m) * lda + kb) + k4);
    }
}
__device__ __forceinline__ void store_a_chunk(uint32_t* a_st, const float4 (&v)[4], int tid)
{
    #pragma unroll
    for (int i = 0; i < 4; i++) {
        int q  = tid + i * 256;
        int m  = q >> 3;
        int k4 = q & 7;
        uint4 t = make_uint4(f2tf32(v[i].x), f2tf32(v[i].y), f2tf32(v[i].z), f2tf32(v[i].w));
        *reinterpret_cast<uint4*>(&a_st[k4 * 512 + ((m ^ k4) * 4)]) = t;
    }
}
__device__ __forceinline__ void load_b_chunk(float4 (&v)[4], const float* __restrict__ Wrows,
                                             int tid)
{
    #pragma unroll
    for (int i = 0; i < 4; i++) {
        int q  = tid + i * 256;
        int k  = q >> 5;
        int n4 = (q & 31) * 4;
        v[i] = __ldg(reinterpret_cast<const float4*>(Wrows + (size_t)k * 128 + n4));
    }
}
__device__ __forceinline__ void store_b_chunk(uint32_t* b_st, const float4 (&v)[4], int tid)
{
    #pragma unroll
    for (int i = 0; i < 4; i++) {
        int q  = tid + i * 256;
        int k  = q >> 5;
        int n4 = (q & 31) * 4;
        uint4 t = make_uint4(f2tf32(v[i].x), f2tf32(v[i].y), f2tf32(v[i].z), f2tf32(v[i].w));
        *reinterpret_cast<uint4*>(&b_st[k * 128 + (n4 ^ ((k & 3) * 8))]) = t;
    }
}

__device__ __forceinline__ void mma_chunk(const uint32_t* __restrict__ Ac,
                                          const uint32_t* __restrict__ Bc,
                                          float (&acc)[4][4][4],
                                          int warp_m, int warp_n, int r, int cq)
{
    #pragma unroll
    for (int ks = 0; ks < 4; ks++) {
        const int k4 = ks * 2;
        uint32_t af[4][4];
        #pragma unroll
        for (int mt = 0; mt < 4; mt++) {
            int m0 = warp_m + mt * 16 + r;
            af[mt][0] = Ac[ k4      * 512 + (( m0      ^  k4     ) * 4) + cq];
            af[mt][1] = Ac[ k4      * 512 + (((m0 + 8) ^  k4     ) * 4) + cq];
            af[mt][2] = Ac[(k4 + 1) * 512 + (( m0      ^ (k4 + 1)) * 4) + cq];
            af[mt][3] = Ac[(k4 + 1) * 512 + (((m0 + 8) ^ (k4 + 1)) * 4) + cq];
        }
        uint32_t bf[4][2];
        #pragma unroll
        for (int nt = 0; nt < 4; nt++) {
            int n  = warp_n + nt * 8 + r;
            int kl = ks * 8 + cq;
            int idx = kl * 128 + (n ^ (cq * 8));
            bf[nt][0] = Bc[idx];
            bf[nt][1] = Bc[idx + 512];
        }
        #pragma unroll
        for (int mt = 0; mt < 4; mt++)
            #pragma unroll
            for (int nt = 0; nt < 4; nt++)
                asm volatile(
                    "mma.sync.aligned.m16n8k8.row.col.f32.tf32.tf32.f32 "
                    "{%0,%1,%2,%3}, {%4,%5,%6,%7}, {%8,%9}, {%0,%1,%2,%3};"
                    : "+f"(acc[mt][nt][0]), "+f"(acc[mt][nt][1]),
                      "+f"(acc[mt][nt][2]), "+f"(acc[mt][nt][3])
                    : "r"(af[mt][0]), "r"(af[mt][1]), "r"(af[mt][2]), "r"(af[mt][3]),
                      "r"(bf[nt][0]), "r"(bf[nt][1]));
    }
}

#define ZERO_ACC4(acc) do {                          \
    _Pragma("unroll") for (int _a = 0; _a < 4; _a++) \
    _Pragma("unroll") for (int _b = 0; _b < 4; _b++) \
    _Pragma("unroll") for (int _c = 0; _c < 4; _c++) acc[_a][_b][_c] = 0.0f; } while (0)

// ---------------- trans GEMM + row-normalize epilogue (unchanged, 256 thr) ----------------
#define TRANS_SMEM_BYTES (16384 * 4)

__global__ void __launch_bounds__(256)
gemm_trans(const float* __restrict__ A, const float* __restrict__ W,
           const float* __restrict__ bias, float* __restrict__ C, int M)
{
    extern __shared__ uint32_t sm[];
    uint32_t* a_st = sm;
    uint32_t* b_st = sm + 8192;
    __shared__ float ssq[128];

    const int tid  = threadIdx.x;
    const int wid  = tid >> 5;
    const int warp_m = (wid & 1) * 64;
    const int warp_n = (wid >> 1) * 32;
    const int lane = tid & 31;
    const int r  = lane >> 2;
    const int cq = lane & 3;
    const int row0 = blockIdx.x * 128;

    if (tid < 128) ssq[tid] = 0.0f;

    float acc[4][4][4];
    ZERO_ACC4(acc);

    float4 va[4], vb[4];
    load_a_chunk(va, A, row0, DFEAT, 0, M, tid);
    load_b_chunk(vb, W, tid);
    store_a_chunk(a_st, va, tid);
    store_b_chunk(b_st, vb, tid);
    __syncthreads();

    #pragma unroll
    for (int c = 0; c < 8; c++) {
        if (c < 7) {
            load_a_chunk(va, A, row0, DFEAT, (c + 1) * 32, M, tid);
            load_b_chunk(vb, W + (size_t)(c + 1) * 32 * 128, tid);
        }
        mma_chunk(a_st + (c & 1) * 4096, b_st + (c & 1) * 4096, acc, warp_m, warp_n, r, cq);
        if (c < 7) {
            store_a_chunk(a_st + ((c + 1) & 1) * 4096, va, tid);
            store_b_chunk(b_st + ((c + 1) & 1) * 4096, vb, tid);
        }
        __syncthreads();
    }

    #pragma unroll
    for (int mt = 0; mt < 4; mt++) {
        #pragma unroll
        for (int half = 0; half < 2; half++) {
            int Rl = warp_m + mt * 16 + r + half * 8;
            float part = 0.0f;
            #pragma unroll
            for (int nt = 0; nt < 4; nt++) {
                int cb = warp_n + nt * 8 + 2 * cq;
                float o0 = acc[mt][nt][half * 2 + 0] + __ldg(bias + cb);
                float o1 = acc[mt][nt][half * 2 + 1] + __ldg(bias + cb + 1);
                acc[mt][nt][half * 2 + 0] = o0;
                acc[mt][nt][half * 2 + 1] = o1;
                part += o0 * o0 + o1 * o1;
            }
            if (row0 + Rl < M) atomicAdd(&ssq[Rl], part);
        }
    }
    __syncthreads();

    #pragma unroll
    for (int mt = 0; mt < 4; mt++) {
        #pragma unroll
        for (int half = 0; half < 2; half++) {
            int Rl = warp_m + mt * 16 + r + half * 8;
            int R = row0 + Rl;
            if (R >= M) continue;
            float s = 1.0f / fmaxf(sqrtf(ssq[Rl]), 1e-12f);
            #pragma unroll
            for (int nt = 0; nt < 4; nt++) {
                int cb = warp_n + nt * 8 + 2 * cq;
                *reinterpret_cast<float2*>(C + (size_t)R * 128 + cb) =
                    make_float2(acc[mt][nt][half * 2] * s, acc[mt][nt][half * 2 + 1] * s);
            }
        }
    }
}

// ---------------- 128-thread fused-layer building blocks ----------------
__device__ __forceinline__ void load_b_chunk128(float4 (&v)[8], const float* __restrict__ Wrows,
                                                int tid)
{
    #pragma unroll
    for (int i = 0; i < 8; i++) {
        int q  = tid + i * 128;
        int k  = q >> 5;
        int n4 = (q & 31) * 4;
        v[i] = __ldg(reinterpret_cast<const float4*>(Wrows + (size_t)k * 128 + n4));
    }
}
__device__ __forceinline__ void store_b_chunk128(uint32_t* b_st, const float4 (&v)[8], int tid)
{
    #pragma unroll
    for (int i = 0; i < 8; i++) {
        int q  = tid + i * 128;
        int k  = q >> 5;
        int n4 = (q & 31) * 4;
        uint4 t = make_uint4(f2tf32(v[i].x), f2tf32(v[i].y), f2tf32(v[i].z), f2tf32(v[i].w));
        *reinterpret_cast<uint4*>(&b_st[k * 128 + (n4 ^ ((k & 3) * 8))]) = t;
    }
}

// 64x64 warp tile: acc[4][8][4]
__device__ __forceinline__ void mma_chunk64(const uint32_t* __restrict__ Ac,
                                            const uint32_t* __restrict__ Bc,
                                            float (&acc)[4][8][4],
                                            int warp_m, int warp_n, int r, int cq)
{
    #pragma unroll
    for (int ks = 0; ks < 4; ks++) {
        const int k4 = ks * 2;
        uint32_t af[4][4];
        #pragma unroll
        for (int mt = 0; mt < 4; mt++) {
            int m0 = warp_m + mt * 16 + r;
            af[mt][0] = Ac[ k4      * 512 + (( m0      ^  k4     ) * 4) + cq];
            af[mt][1] = Ac[ k4      * 512 + (((m0 + 8) ^  k4     ) * 4) + cq];
            af[mt][2] = Ac[(k4 + 1) * 512 + (( m0      ^ (k4 + 1)) * 4) + cq];
            af[mt][3] = Ac[(k4 + 1) * 512 + (((m0 + 8) ^ (k4 + 1)) * 4) + cq];
        }
        uint32_t bf[8][2];
        #pragma unroll
        for (int nt = 0; nt < 8; nt++) {
            int n  = warp_n + nt * 8 + r;
            int kl = ks * 8 + cq;
            int idx = kl * 128 + (n ^ (cq * 8));
            bf[nt][0] = Bc[idx];
            bf[nt][1] = Bc[idx + 512];
        }
        #pragma unroll
        for (int mt = 0; mt < 4; mt++)
            #pragma unroll
            for (int nt = 0; nt < 8; nt++)
                asm volatile(
                    "mma.sync.aligned.m16n8k8.row.col.f32.tf32.tf32.f32 "
                    "{%0,%1,%2,%3}, {%4,%5,%6,%7}, {%8,%9}, {%0,%1,%2,%3};"
                    : "+f"(acc[mt][nt][0]), "+f"(acc[mt][nt][1]),
                      "+f"(acc[mt][nt][2]), "+f"(acc[mt][nt][3])
                    : "r"(af[mt][0]), "r"(af[mt][1]), "r"(af[mt][2]), "r"(af[mt][3]),
                      "r"(bf[nt][0]), "r"(bf[nt][1]));
    }
}

#define ZERO_ACC8(acc) do {                          \
    _Pragma("unroll") for (int _a = 0; _a < 4; _a++) \
    _Pragma("unroll") for (int _b = 0; _b < 8; _b++) \
    _Pragma("unroll") for (int _c = 0; _c < 4; _c++) acc[_a][_b][_c] = 0.0f; } while (0)

// ---------------- fused layer: 128 threads, 4 warps x (64x64), A always in smem --------
// smem words: b_st 2x4096 [0,8192) | h_s [8192,24576) | u_s [24576,40960)  = 160 KB
#define FUSED_SMEM_BYTES (40960 * 4)

__global__ void __launch_bounds__(128, 1)
fused_layer(const float* __restrict__ agg, const float* __restrict__ node_emb,
            const float* __restrict__ w1, const float* __restrict__ desw,
            const float* __restrict__ desb, const float* __restrict__ outw,
            const float* __restrict__ outb, float* __restrict__ C, int M)
{
    extern __shared__ uint32_t sm[];
    uint32_t* b_st = sm;
    uint32_t* h_s  = sm + 8192;
    uint32_t* u_s  = sm + 24576;

    const int tid  = threadIdx.x;
    const int wid  = tid >> 5;
    const int warp_m = (wid & 1) * 64;
    const int warp_n = (wid >> 1) * 64;
    const int lane = tid & 31;
    const int r  = lane >> 2;
    const int cq = lane & 3;
    const int row0 = blockIdx.x * 128;

    float acc[4][8][4];
    float4 vb[8];

    // ---- preload agg tile into h_s (A-chunk layout, 4 planes) ----
    #pragma unroll
    for (int c = 0; c < 4; c++) {
        #pragma unroll
        for (int i = 0; i < 8; i++) {
            int q  = tid + i * 128;
            int m  = q >> 3;
            int k4 = q & 7;
            float4 v = make_float4(0.f, 0.f, 0.f, 0.f);
            if (row0 + m < M)
                v = __ldg(reinterpret_cast<const float4*>(
                        agg + (size_t)(row0 + m) * HID + c * 32) + k4);
            uint4 t = make_uint4(f2tf32(v.x), f2tf32(v.y), f2tf32(v.z), f2tf32(v.w));
            *reinterpret_cast<uint4*>(&h_s[c * 4096 + k4 * 512 + ((m ^ k4) * 4)]) = t;
        }
    }

    // ---- stage 1: h = lrelu(agg @ w1), agg read from h_s, result overwrites h_s ----
    ZERO_ACC8(acc);
    load_b_chunk128(vb, w1, tid);
    store_b_chunk128(b_st, vb, tid);
    __syncthreads();
    #pragma unroll
    for (int c = 0; c < 4; c++) {
        if (c < 3) load_b_chunk128(vb, w1 + (size_t)(c + 1) * 32 * 128, tid);
        mma_chunk64(h_s + c * 4096, b_st + (c & 1) * 4096, acc, warp_m, warp_n, r, cq);
        if (c < 3) store_b_chunk128(b_st + ((c + 1) & 1) * 4096, vb, tid);
        __syncthreads();
    }
    // all MMA reads of h_s complete (barrier above) -> safe to overwrite with h
    #pragma unroll
    for (int mt = 0; mt < 4; mt++)
        #pragma unroll
        for (int half = 0; half < 2; half++) {
            int Rl = warp_m + mt * 16 + r + half * 8;
            #pragma unroll
            for (int nt = 0; nt < 8; nt++) {
                int k = warp_n + nt * 8 + 2 * cq;
                float o0 = lrelu(acc[mt][nt][half * 2 + 0]);
                float o1 = lrelu(acc[mt][nt][half * 2 + 1]);
                int k4 = (k >> 2) & 7;
                int idx = (k >> 5) * 4096 + k4 * 512 + ((Rl ^ k4) * 4) + (k & 3);
                h_s[idx]     = f2tf32(o0);
                h_s[idx + 1] = f2tf32(o1);
            }
        }

    // ---- stage 2: u = lrelu(h @ desw + desb + node_emb) -> u_s ----
    ZERO_ACC8(acc);
    load_b_chunk128(vb, desw, tid);
    store_b_chunk128(b_st, vb, tid);
    __syncthreads();   // also orders h_s writes before stage-2 reads
    #pragma unroll
    for (int c = 0; c < 4; c++) {
        if (c < 3) load_b_chunk128(vb, desw + (size_t)(c + 1) * 32 * 128, tid);
        mma_chunk64(h_s + c * 4096, b_st + (c & 1) * 4096, acc, warp_m, warp_n, r, cq);
        if (c < 3) store_b_chunk128(b_st + ((c + 1) & 1) * 4096, vb, tid);
        __syncthreads();
    }
    #pragma unroll
    for (int mt = 0; mt < 4; mt++)
        #pragma unroll
        for (int half = 0; half < 2; half++) {
            int Rl = warp_m + mt * 16 + r + half * 8;
            int R = row0 + Rl;
            bool ok = (R < M);
            #pragma unroll
            for (int nt = 0; nt < 8; nt++) {
                int k = warp_n + nt * 8 + 2 * cq;
                float o0 = acc[mt][nt][half * 2 + 0] + __ldg(desb + k);
                float o1 = acc[mt][nt][half * 2 + 1] + __ldg(desb + k + 1);
                if (ok) {
                    float2 ne = __ldg(reinterpret_cast<const float2*>(
                                    node_emb + (size_t)R * 128 + k));
                    o0 += ne.x; o1 += ne.y;
                }
                o0 = lrelu(o0); o1 = lrelu(o1);
                int k4 = (k >> 2) & 7;
                int idx = (k >> 5) * 4096 + k4 * 512 + ((Rl ^ k4) * 4) + (k & 3);
                u_s[idx]     = f2tf32(o0);
                u_s[idx + 1] = f2tf32(o1);
            }
        }

    // ---- stage 3: x = lrelu([h|u] @ outw + outb) -> global ----
    ZERO_ACC8(acc);
    load_b_chunk128(vb, outw, tid);
    store_b_chunk128(b_st, vb, tid);
    __syncthreads();   // orders u_s writes before stage-3 reads
    #pragma unroll
    for (int c = 0; c < 8; c++) {
        if (c < 7) load_b_chunk128(vb, outw + (size_t)(c + 1) * 32 * 128, tid);
        const uint32_t* Ac = (c < 4) ? (h_s + c * 4096) : (u_s + (c - 4) * 4096);
        mma_chunk64(Ac, b_st + (c & 1) * 4096, acc, warp_m, warp_n, r, cq);
        if (c < 7) store_b_chunk128(b_st + ((c + 1) & 1) * 4096, vb, tid);
        __syncthreads();
    }
    #pragma unroll
    for (int mt = 0; mt < 4; mt++)
        #pragma unroll
        for (int half = 0; half < 2; half++) {
            int R = row0 + warp_m + mt * 16 + r + half * 8;
            if (R >= M) continue;
            #pragma unroll
            for (int nt = 0; nt < 8; nt++) {
                int cb = warp_n + nt * 8 + 2 * cq;
                float o0 = lrelu(acc[mt][nt][half * 2 + 0] + __ldg(outb + cb));
                float o1 = lrelu(acc[mt][nt][half * 2 + 1] + __ldg(outb + cb + 1));
                *reinterpret_cast<float2*>(C + (size_t)R * 128 + cb) = make_float2(o0, o1);
            }
        }
}

extern "C" void kernel_launch(void* const* d_in, const int* in_sizes, int n_in,
                              void* d_out, int out_size)
{
    const float* feat     = (const float*)d_in[0];
    const float* node_emb = (const float*)d_in[1];
    const int*   src      = (const int*)  d_in[2];
    const int*   dst      = (const int*)  d_in[3];
    const float* ufe      = (const float*)d_in[4];
    const float* trans_w  = (const float*)d_in[5];
    const float* trans_b  = (const float*)d_in[6];
    const float* ws       = (const float*)d_in[7];
    const float* des_w    = (const float*)d_in[8];
    const float* des_b    = (const float*)d_in[9];
    const float* out_w    = (const float*)d_in[10];
    const float* out_b    = (const float*)d_in[11];
    float* out = (float*)d_out;

    float *px, *pagg;
    cudaGetSymbolAddress((void**)&px,   g_x);
    cudaGetSymbolAddress((void**)&pagg, g_agg);

    cudaFuncSetAttribute(fused_layer, cudaFuncAttributeMaxDynamicSharedMemorySize,
                         FUSED_SMEM_BYTES);
    cudaFuncSetAttribute(gemm_trans, cudaFuncAttributeMaxDynamicSharedMemorySize,
                         TRANS_SMEM_BYTES);

    const int gridN = (NNODES + 127) / 128;
    const int gridI = (NITEMS + 127) / 128;
    const int gridE = (NEDGES + 255) / 256;

    // ---- CSR build ----
    hist_kernel<<<gridE, 256>>>(dst);
    scan_blocks_kernel<<<SCAN_NB, SCAN_BS>>>();
    scan_fin_kernel<<<SCAN_NB, SCAN_BS>>>();
    fill_kernel<<<gridE, 256>>>(src, dst);

    // ---- x init ----
    user_copy_norm_kernel<<<(NUSERS + 7) / 8, 256>>>(ufe, px, out + (size_t)NNODES * HID);
    gemm_trans<<<gridI, 256, TRANS_SMEM_BYTES>>>(feat, trans_w, trans_b,
                                                 px + (size_t)NUSERS * HID, NITEMS);

    for (int i = 0; i < KLAYERS; i++) {
        agg_csr_kernel<<<(NNODES + 7) / 8, 256>>>(px, pagg);
        float* cdst = (i == KLAYERS - 1) ? out : px;
        fused_layer<<<gridN, 128, FUSED_SMEM_BYTES>>>(
            pagg, node_emb,
            ws    + (size_t)i * HID * HID,
            des_w + (size_t)i * HID * HID,
            des_b + (size_t)i * HID,
            out_w + (size_t)i * 2 * HID * HID,
            out_b + (size_t)i * HID,
            cdst, NNODES);
    }
}

// round 15
// speedup vs baseline: 1.7640x; 1.7640x over previous
#include <cuda_runtime.h>
#include <cstdint>

#define NUSERS 50000
#define NITEMS 50000
#define NNODES 100000
#define DFEAT  256
#define HID    128
#define NEDGES 1600000
#define KLAYERS 3

#define SCAN_BS   1024
#define SCAN_NB   ((NNODES + SCAN_BS - 1) / SCAN_BS)   // 98

// Scratch (static device globals; allocation is forbidden)
__device__ float g_x  [(size_t)NNODES * HID];
__device__ float g_agg[(size_t)NNODES * HID];
__device__ int   g_cnt[NNODES];            // zero-init at load; self-zeroed each call
__device__ int   g_rowptr[NNODES + 1];
__device__ int   g_cur[NNODES];
__device__ int   g_csr[NEDGES];
__device__ int   g_part[SCAN_NB];

__device__ __forceinline__ uint32_t f2tf32(float f) {
    uint32_t u;
    asm("cvt.rna.tf32.f32 %0, %1;" : "=r"(u) : "f"(f));
    return u;
}
__device__ __forceinline__ float lrelu(float v) { return (v > 0.f) ? v : 0.01f * v; }

// ---------------- CSR construction ----------------
__global__ void hist_kernel(const int* __restrict__ dst)
{
    int e = blockIdx.x * blockDim.x + threadIdx.x;
    if (e < NEDGES) atomicAdd(&g_cnt[__ldg(dst + e)], 1);
}

__global__ void scan_blocks_kernel()
{
    __shared__ int sh[SCAN_BS];
    int t = threadIdx.x, b = blockIdx.x;
    int i = b * SCAN_BS + t;
    sh[t] = (i < NNODES) ? g_cnt[i] : 0;
    if (i < NNODES) g_cnt[i] = 0;          // self-zero for the next call
    __syncthreads();
    #pragma unroll
    for (int off = 1; off < SCAN_BS; off <<= 1) {
        int u = (t >= off) ? sh[t - off] : 0;
        __syncthreads();
        sh[t] += u;
        __syncthreads();
    }
    if (i < NNODES) g_rowptr[i + 1] = sh[t];
    if (t == SCAN_BS - 1) g_part[b] = sh[t];
}

__global__ void scan_fin_kernel()
{
    __shared__ int wsum[32];
    int t = threadIdx.x, b = blockIdx.x;
    int v = (t < b) ? g_part[t] : 0;   // b <= 97 < 1024
    #pragma unroll
    for (int o = 16; o > 0; o >>= 1) v += __shfl_down_sync(0xffffffffu, v, o);
    if ((t & 31) == 0) wsum[t >> 5] = v;
    __syncthreads();
    if (t == 0) {
        int s = 0;
        #pragma unroll
        for (int w = 0; w < 32; w++) s += wsum[w];
        wsum[0] = s;
    }
    __syncthreads();
    int off = wsum[0];
    int i = b * SCAN_BS + t;
    int p = 0;
    if (i < NNODES && t > 0) p = g_rowptr[i];
    __syncthreads();
    if (i < NNODES) {
        g_rowptr[i + 1] += off;
        g_cur[i] = off + p;
        if (i == 0) g_rowptr[0] = 0;
    }
}

__global__ void fill_kernel(const int* __restrict__ src, const int* __restrict__ dst)
{
    int e = blockIdx.x * blockDim.x + threadIdx.x;
    if (e >= NEDGES) return;
    int d = __ldg(dst + e);
    int pos = atomicAdd(&g_cur[d], 1);
    g_csr[pos] = __ldg(src + e);
}

// ---------------- CSR aggregation: agg[n] = sum_{e: dst=n} x[src[e]] ----------------
__global__ void __launch_bounds__(256)
agg_csr_kernel(const float* __restrict__ x, float* __restrict__ agg)
{
    int n = blockIdx.x * 8 + (threadIdx.x >> 5);
    if (n >= NNODES) return;
    const int lane = threadIdx.x & 31;
    const int beg = __ldg(&g_rowptr[n]);
    const int end = __ldg(&g_rowptr[n + 1]);

    float4 acc = make_float4(0.f, 0.f, 0.f, 0.f);
    for (int base = beg; base < end; base += 32) {
        int j = base + lane;
        int my = (j < end) ? __ldg(&g_csr[j]) : 0;
        int cnt = min(32, end - base);
        int t = 0;
        for (; t + 4 <= cnt; t += 4) {
            int s0 = __shfl_sync(0xffffffffu, my, t);
            int s1 = __shfl_sync(0xffffffffu, my, t + 1);
            int s2 = __shfl_sync(0xffffffffu, my, t + 2);
            int s3 = __shfl_sync(0xffffffffu, my, t + 3);
            float4 v0 = __ldg(reinterpret_cast<const float4*>(x + (size_t)s0 * HID) + lane);
            float4 v1 = __ldg(reinterpret_cast<const float4*>(x + (size_t)s1 * HID) + lane);
            float4 v2 = __ldg(reinterpret_cast<const float4*>(x + (size_t)s2 * HID) + lane);
            float4 v3 = __ldg(reinterpret_cast<const float4*>(x + (size_t)s3 * HID) + lane);
            acc.x += v0.x; acc.y += v0.y; acc.z += v0.z; acc.w += v0.w;
            acc.x += v1.x; acc.y += v1.y; acc.z += v1.z; acc.w += v1.w;
            acc.x += v2.x; acc.y += v2.y; acc.z += v2.z; acc.w += v2.w;
            acc.x += v3.x; acc.y += v3.y; acc.z += v3.z; acc.w += v3.w;
        }
        for (; t < cnt; t++) {
            int s = __shfl_sync(0xffffffffu, my, t);
            float4 v = __ldg(reinterpret_cast<const float4*>(x + (size_t)s * HID) + lane);
            acc.x += v.x; acc.y += v.y; acc.z += v.z; acc.w += v.w;
        }
    }
    reinterpret_cast<float4*>(agg + (size_t)n * HID)[lane] = acc;
}

// ---------------- users: copy + row L2-normalize + raw fp32 passthrough ----------------
__global__ void user_copy_norm_kernel(const float* __restrict__ ufe, float* __restrict__ x,
                                      float* __restrict__ pass)
{
    int row = blockIdx.x * 8 + (threadIdx.x >> 5);
    if (row >= NUSERS) return;
    int lane = threadIdx.x & 31;
    float4 v = __ldg(reinterpret_cast<const float4*>(ufe + (size_t)row * HID) + lane);
    reinterpret_cast<float4*>(pass + (size_t)row * HID)[lane] = v;
    float ss = v.x * v.x + v.y * v.y + v.z * v.z + v.w * v.w;
    #pragma unroll
    for (int o = 16; o > 0; o >>= 1) ss += __shfl_xor_sync(0xffffffffu, ss, o);
    float s = 1.0f / fmaxf(sqrtf(ss), 1e-12f);
    v.x *= s; v.y *= s; v.z *= s; v.w *= s;
    reinterpret_cast<float4*>(x + (size_t)row * HID)[lane] = v;
}

// ---------------- shared GEMM building blocks (R13, unchanged) ----------------
__device__ __forceinline__ void load_a_chunk(float4 (&v)[4], const float* __restrict__ A,
                                             int row0, int lda, int kb, int M, int tid)
{
    #pragma unroll
    for (int i = 0; i < 4; i++) {
        int q  = tid + i * 256;
        int m  = q >> 3;
        int k4 = q & 7;
        v[i] = make_float4(0.f, 0.f, 0.f, 0.f);
        if (row0 + m < M)
            v[i] = __ldg(reinterpret_cast<const float4*>(A + (size_t)(row0 + m) * lda + kb) + k4);
    }
}
__device__ __forceinline__ void store_a_chunk(uint32_t* a_st, const float4 (&v)[4], int tid)
{
    #pragma unroll
    for (int i = 0; i < 4; i++) {
        int q  = tid + i * 256;
        int m  = q >> 3;
        int k4 = q & 7;
        uint4 t = make_uint4(f2tf32(v[i].x), f2tf32(v[i].y), f2tf32(v[i].z), f2tf32(v[i].w));
        *reinterpret_cast<uint4*>(&a_st[k4 * 512 + ((m ^ k4) * 4)]) = t;
    }
}
__device__ __forceinline__ void load_b_chunk(float4 (&v)[4], const float* __restrict__ Wrows,
                                             int tid)
{
    #pragma unroll
    for (int i = 0; i < 4; i++) {
        int q  = tid + i * 256;
        int k  = q >> 5;
        int n4 = (q & 31) * 4;
        v[i] = __ldg(reinterpret_cast<const float4*>(Wrows + (size_t)k * 128 + n4));
    }
}
__device__ __forceinline__ void store_b_chunk(uint32_t* b_st, const float4 (&v)[4], int tid)
{
    #pragma unroll
    for (int i = 0; i < 4; i++) {
        int q  = tid + i * 256;
        int k  = q >> 5;
        int n4 = (q & 31) * 4;
        uint4 t = make_uint4(f2tf32(v[i].x), f2tf32(v[i].y), f2tf32(v[i].z), f2tf32(v[i].w));
        *reinterpret_cast<uint4*>(&b_st[k * 128 + (n4 ^ ((k & 3) * 8))]) = t;
    }
}

__device__ __forceinline__ void mma_chunk(const uint32_t* __restrict__ Ac,
                                          const uint32_t* __restrict__ Bc,
                                          float (&acc)[4][4][4],
                                          int warp_m, int warp_n, int r, int cq)
{
    #pragma unroll
    for (int ks = 0; ks < 4; ks++) {
        const int k4 = ks * 2;
        uint32_t af[4][4];
        #pragma unroll
        for (int mt = 0; mt < 4; mt++) {
            int m0 = warp_m + mt * 16 + r;
            af[mt][0] = Ac[ k4      * 512 + (( m0      ^  k4     ) * 4) + cq];
            af[mt][1] = Ac[ k4      * 512 + (((m0 + 8) ^  k4     ) * 4) + cq];
            af[mt][2] = Ac[(k4 + 1) * 512 + (( m0      ^ (k4 + 1)) * 4) + cq];
            af[mt][3] = Ac[(k4 + 1) * 512 + (((m0 + 8) ^ (k4 + 1)) * 4) + cq];
        }
        uint32_t bf[4][2];
        #pragma unroll
        for (int nt = 0; nt < 4; nt++) {
            int n  = warp_n + nt * 8 + r;
            int kl = ks * 8 + cq;
            int idx = kl * 128 + (n ^ (cq * 8));
            bf[nt][0] = Bc[idx];
            bf[nt][1] = Bc[idx + 512];
        }
        #pragma unroll
        for (int mt = 0; mt < 4; mt++)
            #pragma unroll
            for (int nt = 0; nt < 4; nt++)
                asm volatile(
                    "mma.sync.aligned.m16n8k8.row.col.f32.tf32.tf32.f32 "
                    "{%0,%1,%2,%3}, {%4,%5,%6,%7}, {%8,%9}, {%0,%1,%2,%3};"
                    : "+f"(acc[mt][nt][0]), "+f"(acc[mt][nt][1]),
                      "+f"(acc[mt][nt][2]), "+f"(acc[mt][nt][3])
                    : "r"(af[mt][0]), "r"(af[mt][1]), "r"(af[mt][2]), "r"(af[mt][3]),
                      "r"(bf[nt][0]), "r"(bf[nt][1]));
    }
}

#define ZERO_ACC(acc) do {                          \
    _Pragma("unroll") for (int _a = 0; _a < 4; _a++) \
    _Pragma("unroll") for (int _b = 0; _b < 4; _b++) \
    _Pragma("unroll") for (int _c = 0; _c < 4; _c++) acc[_a][_b][_c] = 0.0f; } while (0)

// ---------------- trans GEMM + row-normalize epilogue ----------------
#define TRANS_SMEM_BYTES (16384 * 4)

__global__ void __launch_bounds__(256)
gemm_trans(const float* __restrict__ A, const float* __restrict__ W,
           const float* __restrict__ bias, float* __restrict__ C, int M)
{
    extern __shared__ uint32_t sm[];
    uint32_t* a_st = sm;
    uint32_t* b_st = sm + 8192;
    __shared__ float ssq[128];

    const int tid  = threadIdx.x;
    const int wid  = tid >> 5;
    const int warp_m = (wid & 1) * 64;
    const int warp_n = (wid >> 1) * 32;
    const int lane = tid & 31;
    const int r  = lane >> 2;
    const int cq = lane & 3;
    const int row0 = blockIdx.x * 128;

    if (tid < 128) ssq[tid] = 0.0f;

    float acc[4][4][4];
    ZERO_ACC(acc);

    float4 va[4], vb[4];
    load_a_chunk(va, A, row0, DFEAT, 0, M, tid);
    load_b_chunk(vb, W, tid);
    store_a_chunk(a_st, va, tid);
    store_b_chunk(b_st, vb, tid);
    __syncthreads();

    #pragma unroll
    for (int c = 0; c < 8; c++) {
        if (c < 7) {
            load_a_chunk(va, A, row0, DFEAT, (c + 1) * 32, M, tid);
            load_b_chunk(vb, W + (size_t)(c + 1) * 32 * 128, tid);
        }
        mma_chunk(a_st + (c & 1) * 4096, b_st + (c & 1) * 4096, acc, warp_m, warp_n, r, cq);
        if (c < 7) {
            store_a_chunk(a_st + ((c + 1) & 1) * 4096, va, tid);
            store_b_chunk(b_st + ((c + 1) & 1) * 4096, vb, tid);
        }
        __syncthreads();
    }

    #pragma unroll
    for (int mt = 0; mt < 4; mt++) {
        #pragma unroll
        for (int half = 0; half < 2; half++) {
            int Rl = warp_m + mt * 16 + r + half * 8;
            float part = 0.0f;
            #pragma unroll
            for (int nt = 0; nt < 4; nt++) {
                int cb = warp_n + nt * 8 + 2 * cq;
                float o0 = acc[mt][nt][half * 2 + 0] + __ldg(bias + cb);
                float o1 = acc[mt][nt][half * 2 + 1] + __ldg(bias + cb + 1);
                acc[mt][nt][half * 2 + 0] = o0;
                acc[mt][nt][half * 2 + 1] = o1;
                part += o0 * o0 + o1 * o1;
            }
            if (row0 + Rl < M) atomicAdd(&ssq[Rl], part);
        }
    }
    __syncthreads();

    #pragma unroll
    for (int mt = 0; mt < 4; mt++) {
        #pragma unroll
        for (int half = 0; half < 2; half++) {
            int Rl = warp_m + mt * 16 + r + half * 8;
            int R = row0 + Rl;
            if (R >= M) continue;
            float s = 1.0f / fmaxf(sqrtf(ssq[Rl]), 1e-12f);
            #pragma unroll
            for (int nt = 0; nt < 4; nt++) {
                int cb = warp_n + nt * 8 + 2 * cq;
                *reinterpret_cast<float2*>(C + (size_t)R * 128 + cb) =
                    make_float2(acc[mt][nt][half * 2] * s, acc[mt][nt][half * 2 + 1] * s);
            }
        }
    }
}

// ---------------- fused layer: h -> u -> x (exact R13 structure) ----------------
#define FUSED_SMEM_BYTES (49152 * 4)

__global__ void __launch_bounds__(256, 1)
fused_layer(const float* __restrict__ agg, const float* __restrict__ node_emb,
            const float* __restrict__ w1, const float* __restrict__ desw,
            const float* __restrict__ desb, const float* __restrict__ outw,
            const float* __restrict__ outb, float* __restrict__ C, int M)
{
    extern __shared__ uint32_t sm[];
    uint32_t* a_st = sm;
    uint32_t* b_st = sm + 8192;
    uint32_t* h_s  = sm + 16384;
    uint32_t* u_s  = sm + 32768;

    const int tid  = threadIdx.x;
    const int wid  = tid >> 5;
    const int warp_m = (wid & 1) * 64;
    const int warp_n = (wid >> 1) * 32;
    const int lane = tid & 31;
    const int r  = lane >> 2;
    const int cq = lane & 3;
    const int row0 = blockIdx.x * 128;

    float acc[4][4][4];
    float4 va[4], vb[4];

    // ---- stage 1: h = lrelu(agg @ w1) -> h_s ----
    ZERO_ACC(acc);
    load_a_chunk(va, agg, row0, HID, 0, M, tid);
    load_b_chunk(vb, w1, tid);
    store_a_chunk(a_st, va, tid);
    store_b_chunk(b_st, vb, tid);
    __syncthreads();
    #pragma unroll
    for (int c = 0; c < 4; c++) {
        if (c < 3) {
            load_a_chunk(va, agg, row0, HID, (c + 1) * 32, M, tid);
            load_b_chunk(vb, w1 + (size_t)(c + 1) * 32 * 128, tid);
        }
        mma_chunk(a_st + (c & 1) * 4096, b_st + (c & 1) * 4096, acc, warp_m, warp_n, r, cq);
        if (c < 3) {
            store_a_chunk(a_st + ((c + 1) & 1) * 4096, va, tid);
            store_b_chunk(b_st + ((c + 1) & 1) * 4096, vb, tid);
        }
        __syncthreads();
    }
    #pragma unroll
    for (int mt = 0; mt < 4; mt++)
        #pragma unroll
        for (int half = 0; half < 2; half++) {
            int Rl = warp_m + mt * 16 + r + half * 8;
            #pragma unroll
            for (int nt = 0; nt < 4; nt++) {
                int k = warp_n + nt * 8 + 2 * cq;
                float o0 = lrelu(acc[mt][nt][half * 2 + 0]);
                float o1 = lrelu(acc[mt][nt][half * 2 + 1]);
                int k4 = (k >> 2) & 7;
                int idx = (k >> 5) * 4096 + k4 * 512 + ((Rl ^ k4) * 4) + (k & 3);
                h_s[idx]     = f2tf32(o0);
                h_s[idx + 1] = f2tf32(o1);
            }
        }

    // ---- stage 2: u = lrelu(h @ desw + desb + node_emb) -> u_s ----
    ZERO_ACC(acc);
    load_b_chunk(vb, desw, tid);
    store_b_chunk(b_st, vb, tid);
    __syncthreads();
    #pragma unroll
    for (int c = 0; c < 4; c++) {
        if (c < 3) load_b_chunk(vb, desw + (size_t)(c + 1) * 32 * 128, tid);
        mma_chunk(h_s + c * 4096, b_st + (c & 1) * 4096, acc, warp_m, warp_n, r, cq);
        if (c < 3) store_b_chunk(b_st + ((c + 1) & 1) * 4096, vb, tid);
        __syncthreads();
    }
    #pragma unroll
    for (int mt = 0; mt < 4; mt++)
        #pragma unroll
        for (int half = 0; half < 2; half++) {
            int Rl = warp_m + mt * 16 + r + half * 8;
            int R = row0 + Rl;
            bool ok = (R < M);
            #pragma unroll
            for (int nt = 0; nt < 4; nt++) {
                int k = warp_n + nt * 8 + 2 * cq;
                float o0 = acc[mt][nt][half * 2 + 0] + __ldg(desb + k);
                float o1 = acc[mt][nt][half * 2 + 1] + __ldg(desb + k + 1);
                if (ok) {
                    float2 ne = __ldg(reinterpret_cast<const float2*>(
                                    node_emb + (size_t)R * 128 + k));
                    o0 += ne.x; o1 += ne.y;
                }
                o0 = lrelu(o0); o1 = lrelu(o1);
                int k4 = (k >> 2) & 7;
                int idx = (k >> 5) * 4096 + k4 * 512 + ((Rl ^ k4) * 4) + (k & 3);
                u_s[idx]     = f2tf32(o0);
                u_s[idx + 1] = f2tf32(o1);
            }
        }

    // ---- stage 3: x = lrelu([h|u] @ outw + outb) -> global ----
    ZERO_ACC(acc);
    load_b_chunk(vb, outw, tid);
    store_b_chunk(b_st, vb, tid);
    __syncthreads();
    #pragma unroll
    for (int c = 0; c < 8; c++) {
        if (c < 7) load_b_chunk(vb, outw + (size_t)(c + 1) * 32 * 128, tid);
        const uint32_t* Ac = (c < 4) ? (h_s + c * 4096) : (u_s + (c - 4) * 4096);
        mma_chunk(Ac, b_st + (c & 1) * 4096, acc, warp_m, warp_n, r, cq);
        if (c < 7) store_b_chunk(b_st + ((c + 1) & 1) * 4096, vb, tid);
        __syncthreads();
    }
    #pragma unroll
    for (int mt = 0; mt < 4; mt++)
        #pragma unroll
        for (int half = 0; half < 2; half++) {
            int R = row0 + warp_m + mt * 16 + r + half * 8;
            if (R >= M) continue;
            #pragma unroll
            for (int nt = 0; nt < 4; nt++) {
                int cb = warp_n + nt * 8 + 2 * cq;
                float o0 = lrelu(acc[mt][nt][half * 2 + 0] + __ldg(outb + cb));
                float o1 = lrelu(acc[mt][nt][half * 2 + 1] + __ldg(outb + cb + 1));
                *reinterpret_cast<float2*>(C + (size_t)R * 128 + cb) = make_float2(o0, o1);
            }
        }
}

extern "C" void kernel_launch(void* const* d_in, const int* in_sizes, int n_in,
                              void* d_out, int out_size)
{
    const float* feat     = (const float*)d_in[0];
    const float* node_emb = (const float*)d_in[1];
    const int*   src      = (const int*)  d_in[2];
    const int*   dst      = (const int*)  d_in[3];
    const float* ufe      = (const float*)d_in[4];
    const float* trans_w  = (const float*)d_in[5];
    const float* trans_b  = (const float*)d_in[6];
    const float* ws       = (const float*)d_in[7];
    const float* des_w    = (const float*)d_in[8];
    const float* des_b    = (const float*)d_in[9];
    const float* out_w    = (const float*)d_in[10];
    const float* out_b    = (const float*)d_in[11];
    float* out = (float*)d_out;

    float *px, *pagg;
    cudaGetSymbolAddress((void**)&px,   g_x);
    cudaGetSymbolAddress((void**)&pagg, g_agg);

    cudaFuncSetAttribute(fused_layer, cudaFuncAttributeMaxDynamicSharedMemorySize,
                         FUSED_SMEM_BYTES);
    cudaFuncSetAttribute(gemm_trans, cudaFuncAttributeMaxDynamicSharedMemorySize,
                         TRANS_SMEM_BYTES);

    const int gridN = (NNODES + 127) / 128;
    const int gridI = (NITEMS + 127) / 128;
    const int gridE = (NEDGES + 255) / 256;

    // Fork/join: CSR build on a side stream, x-init on the main stream.
    // Created per call (kernel_launch only runs ~2x: correctness + capture; replays
    // re-execute the captured graph, not this function). No device allocations.
    cudaStream_t s2;
    cudaStreamCreateWithFlags(&s2, cudaStreamNonBlocking);
    cudaEvent_t evF, evJ;
    cudaEventCreateWithFlags(&evF, cudaEventDisableTiming);
    cudaEventCreateWithFlags(&evJ, cudaEventDisableTiming);

    cudaEventRecord(evF, 0);
    cudaStreamWaitEvent(s2, evF, 0);

    // ---- CSR build (side stream) ----
    hist_kernel<<<gridE, 256, 0, s2>>>(dst);
    scan_blocks_kernel<<<SCAN_NB, SCAN_BS, 0, s2>>>();
    scan_fin_kernel<<<SCAN_NB, SCAN_BS, 0, s2>>>();
    fill_kernel<<<gridE, 256, 0, s2>>>(src, dst);
    cudaEventRecord(evJ, s2);

    // ---- x init (main stream, overlapped with CSR build) ----
    user_copy_norm_kernel<<<(NUSERS + 7) / 8, 256>>>(ufe, px, out + (size_t)NNODES * HID);
    gemm_trans<<<gridI, 256, TRANS_SMEM_BYTES>>>(feat, trans_w, trans_b,
                                                 px + (size_t)NUSERS * HID, NITEMS);

    cudaStreamWaitEvent(0, evJ, 0);   // join: layers need both CSR and x

    for (int i = 0; i < KLAYERS; i++) {
        agg_csr_kernel<<<(NNODES + 7) / 8, 256>>>(px, pagg);
        float* cdst = (i == KLAYERS - 1) ? out : px;
        fused_layer<<<gridN, 256, FUSED_SMEM_BYTES>>>(
            pagg, node_emb,
            ws    + (size_t)i * HID * HID,
            des_w + (size_t)i * HID * HID,
            des_b + (size_t)i * HID,
            out_w + (size_t)i * 2 * HID * HID,
            out_b + (size_t)i * HID,
            cdst, NNODES);
    }
}

// round 16
// speedup vs baseline: 1.7953x; 1.0177x over previous
#include <cuda_runtime.h>
#include <cstdint>

#define NUSERS 50000
#define NITEMS 50000
#define NNODES 100000
#define DFEAT  256
#define HID    128
#define NEDGES 1600000
#define KLAYERS 3

#define SCAN_BS   1024
#define SCAN_NB   ((NNODES + SCAN_BS - 1) / SCAN_BS)   // 98

// Scratch (static device globals; allocation is forbidden)
__device__ float g_x  [(size_t)NNODES * HID];
__device__ float g_agg[(size_t)NNODES * HID];
__device__ int   g_cnt[NNODES];            // zero-init at load; self-zeroed each call
__device__ int   g_rowptr[NNODES + 1];
__device__ int   g_cur[NNODES];
__device__ int   g_csr[NEDGES];
__device__ int   g_part[SCAN_NB];

__device__ __forceinline__ uint32_t f2tf32(float f) {
    uint32_t u;
    asm("cvt.rna.tf32.f32 %0, %1;" : "=r"(u) : "f"(f));
    return u;
}
__device__ __forceinline__ float lrelu(float v) { return (v > 0.f) ? v : 0.01f * v; }

// ---------------- CSR construction ----------------
__global__ void hist_kernel(const int* __restrict__ dst)
{
    int e = blockIdx.x * blockDim.x + threadIdx.x;
    if (e < NEDGES) atomicAdd(&g_cnt[__ldg(dst + e)], 1);
}

__global__ void scan_blocks_kernel()
{
    __shared__ int sh[SCAN_BS];
    int t = threadIdx.x, b = blockIdx.x;
    int i = b * SCAN_BS + t;
    sh[t] = (i < NNODES) ? g_cnt[i] : 0;
    if (i < NNODES) g_cnt[i] = 0;          // self-zero for the next call
    __syncthreads();
    #pragma unroll
    for (int off = 1; off < SCAN_BS; off <<= 1) {
        int u = (t >= off) ? sh[t - off] : 0;
        __syncthreads();
        sh[t] += u;
        __syncthreads();
    }
    if (i < NNODES) g_rowptr[i + 1] = sh[t];
    if (t == SCAN_BS - 1) g_part[b] = sh[t];
}

__global__ void scan_fin_kernel()
{
    __shared__ int wsum[32];
    int t = threadIdx.x, b = blockIdx.x;
    int v = (t < b) ? g_part[t] : 0;   // b <= 97 < 1024
    #pragma unroll
    for (int o = 16; o > 0; o >>= 1) v += __shfl_down_sync(0xffffffffu, v, o);
    if ((t & 31) == 0) wsum[t >> 5] = v;
    __syncthreads();
    if (t == 0) {
        int s = 0;
        #pragma unroll
        for (int w = 0; w < 32; w++) s += wsum[w];
        wsum[0] = s;
    }
    __syncthreads();
    int off = wsum[0];
    int i = b * SCAN_BS + t;
    int p = 0;
    if (i < NNODES && t > 0) p = g_rowptr[i];
    __syncthreads();
    if (i < NNODES) {
        g_rowptr[i + 1] += off;
        g_cur[i] = off + p;
        if (i == 0) g_rowptr[0] = 0;
    }
}

__global__ void fill_kernel(const int* __restrict__ src, const int* __restrict__ dst)
{
    int e = blockIdx.x * blockDim.x + threadIdx.x;
    if (e >= NEDGES) return;
    int d = __ldg(dst + e);
    int pos = atomicAdd(&g_cur[d], 1);
    g_csr[pos] = __ldg(src + e);
}

// ---------------- CSR aggregation: agg[n] = sum_{e: dst=n} x[src[e]] ----------------
__global__ void __launch_bounds__(256)
agg_csr_kernel(const float* __restrict__ x, float* __restrict__ agg)
{
    int n = blockIdx.x * 8 + (threadIdx.x >> 5);
    if (n >= NNODES) return;
    const int lane = threadIdx.x & 31;
    const int beg = __ldg(&g_rowptr[n]);
    const int end = __ldg(&g_rowptr[n + 1]);

    float4 acc = make_float4(0.f, 0.f, 0.f, 0.f);
    for (int base = beg; base < end; base += 32) {
        int j = base + lane;
        int my = (j < end) ? __ldg(&g_csr[j]) : 0;
        int cnt = min(32, end - base);
        int t = 0;
        for (; t + 4 <= cnt; t += 4) {
            int s0 = __shfl_sync(0xffffffffu, my, t);
            int s1 = __shfl_sync(0xffffffffu, my, t + 1);
            int s2 = __shfl_sync(0xffffffffu, my, t + 2);
            int s3 = __shfl_sync(0xffffffffu, my, t + 3);
            float4 v0 = __ldg(reinterpret_cast<const float4*>(x + (size_t)s0 * HID) + lane);
            float4 v1 = __ldg(reinterpret_cast<const float4*>(x + (size_t)s1 * HID) + lane);
            float4 v2 = __ldg(reinterpret_cast<const float4*>(x + (size_t)s2 * HID) + lane);
            float4 v3 = __ldg(reinterpret_cast<const float4*>(x + (size_t)s3 * HID) + lane);
            acc.x += v0.x; acc.y += v0.y; acc.z += v0.z; acc.w += v0.w;
            acc.x += v1.x; acc.y += v1.y; acc.z += v1.z; acc.w += v1.w;
            acc.x += v2.x; acc.y += v2.y; acc.z += v2.z; acc.w += v2.w;
            acc.x += v3.x; acc.y += v3.y; acc.z += v3.z; acc.w += v3.w;
        }
        for (; t < cnt; t++) {
            int s = __shfl_sync(0xffffffffu, my, t);
            float4 v = __ldg(reinterpret_cast<const float4*>(x + (size_t)s * HID) + lane);
            acc.x += v.x; acc.y += v.y; acc.z += v.z; acc.w += v.w;
        }
    }
    reinterpret_cast<float4*>(agg + (size_t)n * HID)[lane] = acc;
}

// ---------------- users: copy + row L2-normalize + raw fp32 passthrough ----------------
__global__ void user_copy_norm_kernel(const float* __restrict__ ufe, float* __restrict__ x,
                                      float* __restrict__ pass)
{
    int row = blockIdx.x * 8 + (threadIdx.x >> 5);
    if (row >= NUSERS) return;
    int lane = threadIdx.x & 31;
    float4 v = __ldg(reinterpret_cast<const float4*>(ufe + (size_t)row * HID) + lane);
    reinterpret_cast<float4*>(pass + (size_t)row * HID)[lane] = v;
    float ss = v.x * v.x + v.y * v.y + v.z * v.z + v.w * v.w;
    #pragma unroll
    for (int o = 16; o > 0; o >>= 1) ss += __shfl_xor_sync(0xffffffffu, ss, o);
    float s = 1.0f / fmaxf(sqrtf(ss), 1e-12f);
    v.x *= s; v.y *= s; v.z *= s; v.w *= s;
    reinterpret_cast<float4*>(x + (size_t)row * HID)[lane] = v;
}

// ---------------- 256-thread 128-row GEMM blocks (gemm_trans only, R13) ----------------
__device__ __forceinline__ void load_a_chunk(float4 (&v)[4], const float* __restrict__ A,
                                             int row0, int lda, int kb, int M, int tid)
{
    #pragma unroll
    for (int i = 0; i < 4; i++) {
        int q  = tid + i * 256;
        int m  = q >> 3;
        int k4 = q & 7;
        v[i] = make_float4(0.f, 0.f, 0.f, 0.f);
        if (row0 + m < M)
            v[i] = __ldg(reinterpret_cast<const float4*>(A + (size_t)(row0 + m) * lda + kb) + k4);
    }
}
__device__ __forceinline__ void store_a_chunk(uint32_t* a_st, const float4 (&v)[4], int tid)
{
    #pragma unroll
    for (int i = 0; i < 4; i++) {
        int q  = tid + i * 256;
        int m  = q >> 3;
        int k4 = q & 7;
        uint4 t = make_uint4(f2tf32(v[i].x), f2tf32(v[i].y), f2tf32(v[i].z), f2tf32(v[i].w));
        *reinterpret_cast<uint4*>(&a_st[k4 * 512 + ((m ^ k4) * 4)]) = t;
    }
}
__device__ __forceinline__ void load_b_chunk(float4 (&v)[4], const float* __restrict__ Wrows,
                                             int tid)
{
    #pragma unroll
    for (int i = 0; i < 4; i++) {
        int q  = tid + i * 256;
        int k  = q >> 5;
        int n4 = (q & 31) * 4;
        v[i] = __ldg(reinterpret_cast<const float4*>(Wrows + (size_t)k * 128 + n4));
    }
}
__device__ __forceinline__ void store_b_chunk(uint32_t* b_st, const float4 (&v)[4], int tid)
{
    #pragma unroll
    for (int i = 0; i < 4; i++) {
        int q  = tid + i * 256;
        int k  = q >> 5;
        int n4 = (q & 31) * 4;
        uint4 t = make_uint4(f2tf32(v[i].x), f2tf32(v[i].y), f2tf32(v[i].z), f2tf32(v[i].w));
        *reinterpret_cast<uint4*>(&b_st[k * 128 + (n4 ^ ((k & 3) * 8))]) = t;
    }
}

__device__ __forceinline__ void mma_chunk(const uint32_t* __restrict__ Ac,
                                          const uint32_t* __restrict__ Bc,
                                          float (&acc)[4][4][4],
                                          int warp_m, int warp_n, int r, int cq)
{
    #pragma unroll
    for (int ks = 0; ks < 4; ks++) {
        const int k4 = ks * 2;
        uint32_t af[4][4];
        #pragma unroll
        for (int mt = 0; mt < 4; mt++) {
            int m0 = warp_m + mt * 16 + r;
            af[mt][0] = Ac[ k4      * 512 + (( m0      ^  k4     ) * 4) + cq];
            af[mt][1] = Ac[ k4      * 512 + (((m0 + 8) ^  k4     ) * 4) + cq];
            af[mt][2] = Ac[(k4 + 1) * 512 + (( m0      ^ (k4 + 1)) * 4) + cq];
            af[mt][3] = Ac[(k4 + 1) * 512 + (((m0 + 8) ^ (k4 + 1)) * 4) + cq];
        }
        uint32_t bf[4][2];
        #pragma unroll
        for (int nt = 0; nt < 4; nt++) {
            int n  = warp_n + nt * 8 + r;
            int kl = ks * 8 + cq;
            int idx = kl * 128 + (n ^ (cq * 8));
            bf[nt][0] = Bc[idx];
            bf[nt][1] = Bc[idx + 512];
        }
        #pragma unroll
        for (int mt = 0; mt < 4; mt++)
            #pragma unroll
            for (int nt = 0; nt < 4; nt++)
                asm volatile(
                    "mma.sync.aligned.m16n8k8.row.col.f32.tf32.tf32.f32 "
                    "{%0,%1,%2,%3}, {%4,%5,%6,%7}, {%8,%9}, {%0,%1,%2,%3};"
                    : "+f"(acc[mt][nt][0]), "+f"(acc[mt][nt][1]),
                      "+f"(acc[mt][nt][2]), "+f"(acc[mt][nt][3])
                    : "r"(af[mt][0]), "r"(af[mt][1]), "r"(af[mt][2]), "r"(af[mt][3]),
                      "r"(bf[nt][0]), "r"(bf[nt][1]));
    }
}

#define ZERO_ACC(acc) do {                          \
    _Pragma("unroll") for (int _a = 0; _a < 4; _a++) \
    _Pragma("unroll") for (int _b = 0; _b < 4; _b++) \
    _Pragma("unroll") for (int _c = 0; _c < 4; _c++) acc[_a][_b][_c] = 0.0f; } while (0)

// ---------------- trans GEMM + row-normalize epilogue (unchanged) ----------------
#define TRANS_SMEM_BYTES (16384 * 4)

__global__ void __launch_bounds__(256)
gemm_trans(const float* __restrict__ A, const float* __restrict__ W,
           const float* __restrict__ bias, float* __restrict__ C, int M)
{
    extern __shared__ uint32_t sm[];
    uint32_t* a_st = sm;
    uint32_t* b_st = sm + 8192;
    __shared__ float ssq[128];

    const int tid  = threadIdx.x;
    const int wid  = tid >> 5;
    const int warp_m = (wid & 1) * 64;
    const int warp_n = (wid >> 1) * 32;
    const int lane = tid & 31;
    const int r  = lane >> 2;
    const int cq = lane & 3;
    const int row0 = blockIdx.x * 128;

    if (tid < 128) ssq[tid] = 0.0f;

    float acc[4][4][4];
    ZERO_ACC(acc);

    float4 va[4], vb[4];
    load_a_chunk(va, A, row0, DFEAT, 0, M, tid);
    load_b_chunk(vb, W, tid);
    store_a_chunk(a_st, va, tid);
    store_b_chunk(b_st, vb, tid);
    __syncthreads();

    #pragma unroll
    for (int c = 0; c < 8; c++) {
        if (c < 7) {
            load_a_chunk(va, A, row0, DFEAT, (c + 1) * 32, M, tid);
            load_b_chunk(vb, W + (size_t)(c + 1) * 32 * 128, tid);
        }
        mma_chunk(a_st + (c & 1) * 4096, b_st + (c & 1) * 4096, acc, warp_m, warp_n, r, cq);
        if (c < 7) {
            store_a_chunk(a_st + ((c + 1) & 1) * 4096, va, tid);
            store_b_chunk(b_st + ((c + 1) & 1) * 4096, vb, tid);
        }
        __syncthreads();
    }

    #pragma unroll
    for (int mt = 0; mt < 4; mt++) {
        #pragma unroll
        for (int half = 0; half < 2; half++) {
            int Rl = warp_m + mt * 16 + r + half * 8;
            float part = 0.0f;
            #pragma unroll
            for (int nt = 0; nt < 4; nt++) {
                int cb = warp_n + nt * 8 + 2 * cq;
                float o0 = acc[mt][nt][half * 2 + 0] + __ldg(bias + cb);
                float o1 = acc[mt][nt][half * 2 + 1] + __ldg(bias + cb + 1);
                acc[mt][nt][half * 2 + 0] = o0;
                acc[mt][nt][half * 2 + 1] = o1;
                part += o0 * o0 + o1 * o1;
            }
            if (row0 + Rl < M) atomicAdd(&ssq[Rl], part);
        }
    }
    __syncthreads();

    #pragma unroll
    for (int mt = 0; mt < 4; mt++) {
        #pragma unroll
        for (int half = 0; half < 2; half++) {
            int Rl = warp_m + mt * 16 + r + half * 8;
            int R = row0 + Rl;
            if (R >= M) continue;
            float s = 1.0f / fmaxf(sqrtf(ssq[Rl]), 1e-12f);
            #pragma unroll
            for (int nt = 0; nt < 4; nt++) {
                int cb = warp_n + nt * 8 + 2 * cq;
                *reinterpret_cast<float2*>(C + (size_t)R * 128 + cb) =
                    make_float2(acc[mt][nt][half * 2] * s, acc[mt][nt][half * 2 + 1] * s);
            }
        }
    }
}

// ---------------- 64-row fused-layer building blocks (2 CTAs/SM) ----------------
// A chunk: 64 rows x 32 k = 2048 words; word(m, kl) = (kl>>2)*256 + ((m^(kl>>2))*4) + (kl&3)
// B chunk: unchanged 4096 words.
__device__ __forceinline__ void load_a_chunk64(float4 (&v)[2], const float* __restrict__ A,
                                               int row0, int kb, int M, int tid)
{
    #pragma unroll
    for (int i = 0; i < 2; i++) {
        int q  = tid + i * 256;   // 0..511
        int m  = q >> 3;          // 0..63
        int k4 = q & 7;
        v[i] = make_float4(0.f, 0.f, 0.f, 0.f);
        if (row0 + m < M)
            v[i] = __ldg(reinterpret_cast<const float4*>(A + (size_t)(row0 + m) * HID + kb) + k4);
    }
}
__device__ __forceinline__ void store_a_chunk64(uint32_t* a_st, const float4 (&v)[2], int tid)
{
    #pragma unroll
    for (int i = 0; i < 2; i++) {
        int q  = tid + i * 256;
        int m  = q >> 3;
        int k4 = q & 7;
        uint4 t = make_uint4(f2tf32(v[i].x), f2tf32(v[i].y), f2tf32(v[i].z), f2tf32(v[i].w));
        *reinterpret_cast<uint4*>(&a_st[k4 * 256 + ((m ^ k4) * 4)]) = t;
    }
}

// 32x32 warp tile: acc[2][4][4]
__device__ __forceinline__ void mma_chunk32(const uint32_t* __restrict__ Ac,
                                            const uint32_t* __restrict__ Bc,
                                            float (&acc)[2][4][4],
                                            int warp_m, int warp_n, int r, int cq)
{
    #pragma unroll
    for (int ks = 0; ks < 4; ks++) {
        const int k4 = ks * 2;
        uint32_t af[2][4];
        #pragma unroll
        for (int mt = 0; mt < 2; mt++) {
            int m0 = warp_m + mt * 16 + r;
            af[mt][0] = Ac[ k4      * 256 + (( m0      ^  k4     ) * 4) + cq];
            af[mt][1] = Ac[ k4      * 256 + (((m0 + 8) ^  k4     ) * 4) + cq];
            af[mt][2] = Ac[(k4 + 1) * 256 + (( m0      ^ (k4 + 1)) * 4) + cq];
            af[mt][3] = Ac[(k4 + 1) * 256 + (((m0 + 8) ^ (k4 + 1)) * 4) + cq];
        }
        uint32_t bf[4][2];
        #pragma unroll
        for (int nt = 0; nt < 4; nt++) {
            int n  = warp_n + nt * 8 + r;
            int kl = ks * 8 + cq;
            int idx = kl * 128 + (n ^ (cq * 8));
            bf[nt][0] = Bc[idx];
            bf[nt][1] = Bc[idx + 512];
        }
        #pragma unroll
        for (int mt = 0; mt < 2; mt++)
            #pragma unroll
            for (int nt = 0; nt < 4; nt++)
                asm volatile(
                    "mma.sync.aligned.m16n8k8.row.col.f32.tf32.tf32.f32 "
                    "{%0,%1,%2,%3}, {%4,%5,%6,%7}, {%8,%9}, {%0,%1,%2,%3};"
                    : "+f"(acc[mt][nt][0]), "+f"(acc[mt][nt][1]),
                      "+f"(acc[mt][nt][2]), "+f"(acc[mt][nt][3])
                    : "r"(af[mt][0]), "r"(af[mt][1]), "r"(af[mt][2]), "r"(af[mt][3]),
                      "r"(bf[nt][0]), "r"(bf[nt][1]));
    }
}

#define ZERO_ACC2(acc) do {                          \
    _Pragma("unroll") for (int _a = 0; _a < 2; _a++) \
    _Pragma("unroll") for (int _b = 0; _b < 4; _b++) \
    _Pragma("unroll") for (int _c = 0; _c < 4; _c++) acc[_a][_b][_c] = 0.0f; } while (0)

// ---------------- fused layer: 64-row tile, 8 warps x (32x32), 2 CTAs/SM ----------------
// smem words: b_st 2x4096 [0,8192) | h_s [8192,16384) | u_s [16384,24576)  = 96 KB
#define FUSED_SMEM_BYTES (24576 * 4)

__global__ void __launch_bounds__(256, 2)
fused_layer(const float* __restrict__ agg, const float* __restrict__ node_emb,
            const float* __restrict__ w1, const float* __restrict__ desw,
            const float* __restrict__ desb, const float* __restrict__ outw,
            const float* __restrict__ outb, float* __restrict__ C, int M)
{
    extern __shared__ uint32_t sm[];
    uint32_t* b_st = sm;
    uint32_t* h_s  = sm + 8192;
    uint32_t* u_s  = sm + 16384;

    const int tid  = threadIdx.x;
    const int wid  = tid >> 5;
    const int warp_m = (wid & 1) * 32;
    const int warp_n = (wid >> 1) * 32;
    const int lane = tid & 31;
    const int r  = lane >> 2;
    const int cq = lane & 3;
    const int row0 = blockIdx.x * 64;

    float acc[2][4][4];
    float4 va[2], vb[4];

    // ---- stage 1: h = lrelu(agg @ w1) -> h_s ----
    ZERO_ACC2(acc);
    load_a_chunk64(va, agg, row0, 0, M, tid);
    load_b_chunk(vb, w1, tid);
    store_a_chunk64(h_s, va, tid);            // use h_s plane 0 as A buf? no: A double-buffers
    // A chunks live in their own slots inside h_s? They must not: stage-1 A is agg.
    // Use u_s as the A double buffer for stage 1 (u_s is not written until stage 2).
    store_b_chunk(b_st, vb, tid);
    __syncthreads();
    // Correction path: stage-1 A chunks alternate between h_s[0..2048) and u_s[0..2048)?
    // Simpler: A chunk c for stage 1 is stored at u_s + (c&1)*2048 (u_s unused until stage 2).
    // The initial store above targeted h_s; redo bookkeeping: treat buffer0 = h_s[0..2048).
    #pragma unroll
    for (int c = 0; c < 4; c++) {
        if (c < 3) {
            load_a_chunk64(va, agg, row0, (c + 1) * 32, M, tid);
            load_b_chunk(vb, w1 + (size_t)(c + 1) * 32 * 128, tid);
        }
        const uint32_t* Ac = (c & 1) ? (u_s) : (h_s);
        mma_chunk32(Ac, b_st + (c & 1) * 4096, acc, warp_m, warp_n, r, cq);
        if (c < 3) {
            uint32_t* An = ((c + 1) & 1) ? u_s : h_s;
            store_a_chunk64(An, va, tid);
            store_b_chunk(b_st + ((c + 1) & 1) * 4096, vb, tid);
        }
        __syncthreads();
    }
    // write h (tf32) into h_s, full 4-chunk layout
    #pragma unroll
    for (int mt = 0; mt < 2; mt++)
        #pragma unroll
        for (int half = 0; half < 2; half++) {
            int Rl = warp_m + mt * 16 + r + half * 8;
            #pragma unroll
            for (int nt = 0; nt < 4; nt++) {
                int k = warp_n + nt * 8 + 2 * cq;
                float o0 = lrelu(acc[mt][nt][half * 2 + 0]);
                float o1 = lrelu(acc[mt][nt][half * 2 + 1]);
                int k4 = (k >> 2) & 7;
                int idx = (k >> 5) * 2048 + k4 * 256 + ((Rl ^ k4) * 4) + (k & 3);
                h_s[idx]     = f2tf32(o0);
                h_s[idx + 1] = f2tf32(o1);
            }
        }

    // ---- stage 2: u = lrelu(h @ desw + desb + node_emb) -> u_s ----
    ZERO_ACC2(acc);
    load_b_chunk(vb, desw, tid);
    store_b_chunk(b_st, vb, tid);
    __syncthreads();   // orders h_s writes before stage-2 reads
    #pragma unroll
    for (int c = 0; c < 4; c++) {
        if (c < 3) load_b_chunk(vb, desw + (size_t)(c + 1) * 32 * 128, tid);
        mma_chunk32(h_s + c * 2048, b_st + (c & 1) * 4096, acc, warp_m, warp_n, r, cq);
        if (c < 3) store_b_chunk(b_st + ((c + 1) & 1) * 4096, vb, tid);
        __syncthreads();
    }
    #pragma unroll
    for (int mt = 0; mt < 2; mt++)
        #pragma unroll
        for (int half = 0; half < 2; half++) {
            int Rl = warp_m + mt * 16 + r + half * 8;
            int R = row0 + Rl;
            bool ok = (R < M);
            #pragma unroll
            for (int nt = 0; nt < 4; nt++) {
                int k = warp_n + nt * 8 + 2 * cq;
                float o0 = acc[mt][nt][half * 2 + 0] + __ldg(desb + k);
                float o1 = acc[mt][nt][half * 2 + 1] + __ldg(desb + k + 1);
                if (ok) {
                    float2 ne = __ldg(reinterpret_cast<const float2*>(
                                    node_emb + (size_t)R * 128 + k));
                    o0 += ne.x; o1 += ne.y;
                }
                o0 = lrelu(o0); o1 = lrelu(o1);
                int k4 = (k >> 2) & 7;
                int idx = (k >> 5) * 2048 + k4 * 256 + ((Rl ^ k4) * 4) + (k & 3);
                u_s[idx]     = f2tf32(o0);
                u_s[idx + 1] = f2tf32(o1);
            }
        }

    // ---- stage 3: x = lrelu([h|u] @ outw + outb) -> global ----
    ZERO_ACC2(acc);
    load_b_chunk(vb, outw, tid);
    store_b_chunk(b_st, vb, tid);
    __syncthreads();   // orders u_s writes before stage-3 reads
    #pragma unroll
    for (int c = 0; c < 8; c++) {
        if (c < 7) load_b_chunk(vb, outw + (size_t)(c + 1) * 32 * 128, tid);
        const uint32_t* Ac = (c < 4) ? (h_s + c * 2048) : (u_s + (c - 4) * 2048);
        mma_chunk32(Ac, b_st + (c & 1) * 4096, acc, warp_m, warp_n, r, cq);
        if (c < 7) store_b_chunk(b_st + ((c + 1) & 1) * 4096, vb, tid);
        __syncthreads();
    }
    #pragma unroll
    for (int mt = 0; mt < 2; mt++)
        #pragma unroll
        for (int half = 0; half < 2; half++) {
            int R = row0 + warp_m + mt * 16 + r + half * 8;
            if (R >= M) continue;
            #pragma unroll
            for (int nt = 0; nt < 4; nt++) {
                int cb = warp_n + nt * 8 + 2 * cq;
                float o0 = lrelu(acc[mt][nt][half * 2 + 0] + __ldg(outb + cb));
                float o1 = lrelu(acc[mt][nt][half * 2 + 1] + __ldg(outb + cb + 1));
                *reinterpret_cast<float2*>(C + (size_t)R * 128 + cb) = make_float2(o0, o1);
            }
        }
}

extern "C" void kernel_launch(void* const* d_in, const int* in_sizes, int n_in,
                              void* d_out, int out_size)
{
    const float* feat     = (const float*)d_in[0];
    const float* node_emb = (const float*)d_in[1];
    const int*   src      = (const int*)  d_in[2];
    const int*   dst      = (const int*)  d_in[3];
    const float* ufe      = (const float*)d_in[4];
    const float* trans_w  = (const float*)d_in[5];
    const float* trans_b  = (const float*)d_in[6];
    const float* ws       = (const float*)d_in[7];
    const float* des_w    = (const float*)d_in[8];
    const float* des_b    = (const float*)d_in[9];
    const float* out_w    = (const float*)d_in[10];
    const float* out_b    = (const float*)d_in[11];
    float* out = (float*)d_out;

    float *px, *pagg;
    cudaGetSymbolAddress((void**)&px,   g_x);
    cudaGetSymbolAddress((void**)&pagg, g_agg);

    cudaFuncSetAttribute(fused_layer, cudaFuncAttributeMaxDynamicSharedMemorySize,
                         FUSED_SMEM_BYTES);
    cudaFuncSetAttribute(gemm_trans, cudaFuncAttributeMaxDynamicSharedMemorySize,
                         TRANS_SMEM_BYTES);

    const int gridN = (NNODES + 63) / 64;      // 64-row fused tiles
    const int gridI = (NITEMS + 127) / 128;
    const int gridE = (NEDGES + 255) / 256;

    // Fork/join: CSR build on a side stream, x-init on the main stream (R15, kept).
    cudaStream_t s2;
    cudaStreamCreateWithFlags(&s2, cudaStreamNonBlocking);
    cudaEvent_t evF, evJ;
    cudaEventCreateWithFlags(&evF, cudaEventDisableTiming);
    cudaEventCreateWithFlags(&evJ, cudaEventDisableTiming);

    cudaEventRecord(evF, 0);
    cudaStreamWaitEvent(s2, evF, 0);

    // ---- CSR build (side stream) ----
    hist_kernel<<<gridE, 256, 0, s2>>>(dst);
    scan_blocks_kernel<<<SCAN_NB, SCAN_BS, 0, s2>>>();
    scan_fin_kernel<<<SCAN_NB, SCAN_BS, 0, s2>>>();
    fill_kernel<<<gridE, 256, 0, s2>>>(src, dst);
    cudaEventRecord(evJ, s2);

    // ---- x init (main stream, overlapped with CSR build) ----
    user_copy_norm_kernel<<<(NUSERS + 7) / 8, 256>>>(ufe, px, out + (size_t)NNODES * HID);
    gemm_trans<<<gridI, 256, TRANS_SMEM_BYTES>>>(feat, trans_w, trans_b,
                                                 px + (size_t)NUSERS * HID, NITEMS);

    cudaStreamWaitEvent(0, evJ, 0);   // join: layers need both CSR and x

    for (int i = 0; i < KLAYERS; i++) {
        agg_csr_kernel<<<(NNODES + 7) / 8, 256>>>(px, pagg);
        float* cdst = (i == KLAYERS - 1) ? out : px;
        fused_layer<<<gridN, 256, FUSED_SMEM_BYTES>>>(
            pagg, node_emb,
            ws    + (size_t)i * HID * HID,
            des_w + (size_t)i * HID * HID,
            des_b + (size_t)i * HID,
            out_w + (size_t)i * 2 * HID * HID,
            out_b + (size_t)i * HID,
            cdst, NNODES);
    }
}